// round 7
// baseline (speedup 1.0000x reference)
#include <cuda_runtime.h>
#include <cuda_bf16.h>
#include <math.h>
#include <stdint.h>

#define TT 2048          // sequence length
#define CC 2048          // embed dim
#define HH 16            // heads
#define DD 128           // head dim
#define NBITS 7
#define BKH 16           // k-slab for bf16x3 core
#define RSW 12           // u32 words per row per split tile (8 used + 4 pad)
#define FIXCAP 8192

// ---------------- scratch (static device globals; no allocation) ----------------
__device__ float g_Qraw[(size_t)TT * CC];
__device__ float g_Kraw[(size_t)TT * CC];
__device__ float g_Vraw[(size_t)TT * CC];
__device__ float g_Qn[(size_t)HH * TT * DD];   // [h][t][d] rope+rmsnorm
__device__ float g_Kn[(size_t)HH * TT * DD];
__device__ float g_Vt[(size_t)CC * TT];        // Vraw transposed: [h*128+d][t]
__device__ float g_S[(size_t)HH * TT * TT];    // scores -> softmax weights
__device__ float g_Y[(size_t)TT * CC];         // attention output, [t][h*128+d]
__device__ int   g_qc[HH * TT];
__device__ int   g_kc[HH * TT];
__device__ int   g_fixcnt;
__device__ int   g_fixlist[FIXCAP];

// ============================================================
// bf16x3 emulated-fp32 GEMM core (all GEMMs)
// ============================================================
__device__ __forceinline__ void split2(float x, float& hi, float& lo)
{
    hi = __bfloat162float(__float2bfloat16_rn(x));
    lo = x - hi;
}

__device__ __forceinline__ uint32_t pack2(float a, float b)
{
    __nv_bfloat162 t = __floats2bfloat162_rn(a, b);   // a -> low half
    return *reinterpret_cast<uint32_t*>(&t);
}

__device__ __forceinline__ void mma_bf16(float d[4], const uint32_t a[4],
                                         uint32_t b0, uint32_t b1)
{
    asm volatile(
        "mma.sync.aligned.m16n8k16.row.col.f32.bf16.bf16.f32 "
        "{%0,%1,%2,%3}, {%4,%5,%6,%7}, {%8,%9}, {%0,%1,%2,%3};"
        : "+f"(d[0]), "+f"(d[1]), "+f"(d[2]), "+f"(d[3])
        : "r"(a[0]), "r"(a[1]), "r"(a[2]), "r"(a[3]), "r"(b0), "r"(b1));
}

// C = A(m0+128 x kend) . B^T; A row-major lda, B row-major ldb. kend % 16 == 0.
__device__ __forceinline__ void gemm_core(const float* __restrict__ A, int lda,
                                          const float* __restrict__ B, int ldb,
                                          int m0, int n0, int kend,
                                          float acc[2][8][4])
{
    __shared__ uint32_t sA[2][128 * RSW];
    __shared__ uint32_t sB[2][128 * RSW];

    const int tid = threadIdx.x, lane = tid & 31, warp = tid >> 5;
    const int g = lane >> 2, tig = lane & 3;
    const int wm = (warp & 3) * 32, wn = (warp >> 2) * 64;

#pragma unroll
    for (int tm = 0; tm < 2; tm++)
#pragma unroll
        for (int tn = 0; tn < 8; tn++)
#pragma unroll
            for (int e = 0; e < 4; e++) acc[tm][tn][e] = 0.f;

    // producer mapping: slot = tid + 256*i -> row m = slot>>2, float4 j = slot&3
    float4 pa[2], pb[2];
#pragma unroll
    for (int i = 0; i < 2; i++) {
        int slot = tid + 256 * i, m = slot >> 2, j = slot & 3;
        pa[i] = *(const float4*)(A + (size_t)(m0 + m) * lda + 4 * j);
        pb[i] = *(const float4*)(B + (size_t)(n0 + m) * ldb + 4 * j);
    }

    for (int k0 = 0; k0 < kend; k0 += BKH) {
#pragma unroll
        for (int i = 0; i < 2; i++) {
            int slot = tid + 256 * i, m = slot >> 2, j = slot & 3;
            float h0, l0, h1, l1, h2, l2, h3, l3;
            split2(pa[i].x, h0, l0); split2(pa[i].y, h1, l1);
            split2(pa[i].z, h2, l2); split2(pa[i].w, h3, l3);
            sA[0][m * RSW + 2 * j]     = pack2(h0, h1);
            sA[0][m * RSW + 2 * j + 1] = pack2(h2, h3);
            sA[1][m * RSW + 2 * j]     = pack2(l0, l1);
            sA[1][m * RSW + 2 * j + 1] = pack2(l2, l3);
            split2(pb[i].x, h0, l0); split2(pb[i].y, h1, l1);
            split2(pb[i].z, h2, l2); split2(pb[i].w, h3, l3);
            sB[0][m * RSW + 2 * j]     = pack2(h0, h1);
            sB[0][m * RSW + 2 * j + 1] = pack2(h2, h3);
            sB[1][m * RSW + 2 * j]     = pack2(l0, l1);
            sB[1][m * RSW + 2 * j + 1] = pack2(l2, l3);
        }
        __syncthreads();

        if (k0 + BKH < kend) {
#pragma unroll
            for (int i = 0; i < 2; i++) {
                int slot = tid + 256 * i, m = slot >> 2, j = slot & 3;
                pa[i] = *(const float4*)(A + (size_t)(m0 + m) * lda + k0 + BKH + 4 * j);
                pb[i] = *(const float4*)(B + (size_t)(n0 + m) * ldb + k0 + BKH + 4 * j);
            }
        }

        uint32_t ar[2][2][4];
#pragma unroll
        for (int s = 0; s < 2; s++)
#pragma unroll
            for (int tm = 0; tm < 2; tm++) {
                int r = wm + 16 * tm + g;
                ar[s][tm][0] = sA[s][r * RSW + tig];
                ar[s][tm][1] = sA[s][(r + 8) * RSW + tig];
                ar[s][tm][2] = sA[s][r * RSW + tig + 4];
                ar[s][tm][3] = sA[s][(r + 8) * RSW + tig + 4];
            }

#pragma unroll
        for (int tn = 0; tn < 8; tn++) {
            int c = wn + 8 * tn + g;
            uint32_t bh0 = sB[0][c * RSW + tig];
            uint32_t bh1 = sB[0][c * RSW + tig + 4];
            uint32_t bl0 = sB[1][c * RSW + tig];
            uint32_t bl1 = sB[1][c * RSW + tig + 4];
#pragma unroll
            for (int tm = 0; tm < 2; tm++) {
                mma_bf16(acc[tm][tn], ar[1][tm], bh0, bh1);  // lo*hi
                mma_bf16(acc[tm][tn], ar[0][tm], bl0, bl1);  // hi*lo
                mma_bf16(acc[tm][tn], ar[0][tm], bh0, bh1);  // hi*hi
            }
        }
        __syncthreads();
    }
}

__device__ __forceinline__ void epi_store(float* __restrict__ C, int ldc,
                                          int m0, int n0, float acc[2][8][4])
{
    const int lane = threadIdx.x & 31, warp = threadIdx.x >> 5;
    const int g = lane >> 2, tig = lane & 3;
    const int wm = (warp & 3) * 32, wn = (warp >> 2) * 64;
#pragma unroll
    for (int tm = 0; tm < 2; tm++)
#pragma unroll
        for (int tn = 0; tn < 8; tn++) {
            int r = m0 + wm + 16 * tm + g;
            int c = n0 + wn + 8 * tn + 2 * tig;
            *(float2*)(C + (size_t)r * ldc + c) = make_float2(acc[tm][tn][0], acc[tm][tn][1]);
            *(float2*)(C + (size_t)(r + 8) * ldc + c) = make_float2(acc[tm][tn][2], acc[tm][tn][3]);
        }
}

// ---------------- QKV projections ----------------
__global__ __launch_bounds__(256, 1) void k_qkv_tc(const float* __restrict__ x,
                                                   const float* __restrict__ Wq,
                                                   const float* __restrict__ Wk,
                                                   const float* __restrict__ Wv)
{
    const float* B = (blockIdx.z == 0) ? Wq : (blockIdx.z == 1) ? Wk : Wv;
    float* C = (blockIdx.z == 0) ? g_Qraw : (blockIdx.z == 1) ? g_Kraw : g_Vraw;
    float acc[2][8][4];
    gemm_core(x, CC, B, CC, blockIdx.y * 128, blockIdx.x * 128, CC, acc);
    epi_store(C, CC, blockIdx.y * 128, blockIdx.x * 128, acc);
}

// ---------------- output projection ----------------
__global__ __launch_bounds__(256, 1) void k_proj_tc(const float* __restrict__ Wproj,
                                                    float* __restrict__ out)
{
    float acc[2][8][4];
    gemm_core(g_Y, CC, Wproj, CC, blockIdx.y * 128, blockIdx.x * 128, CC, acc);
    epi_store(out, CC, blockIdx.y * 128, blockIdx.x * 128, acc);
}

// ---------------- masked scores ----------------
__global__ __launch_bounds__(256, 1) void k_scores_tc()
{
    if (blockIdx.x > blockIdx.y) return;   // upper-triangular blocks never read
    const int h = blockIdx.z;
    const float* A = g_Qn + (size_t)h * TT * DD;
    const float* B = g_Kn + (size_t)h * TT * DD;
    float* Sp = g_S + (size_t)h * TT * TT;
    const int m0 = blockIdx.y * 128, n0 = blockIdx.x * 128;

    float acc[2][8][4];
    gemm_core(A, DD, B, DD, m0, n0, DD, acc);

    const float scale = 0.08838834764831845f;  // 1/sqrt(128)
    const int lane = threadIdx.x & 31, warp = threadIdx.x >> 5;
    const int g = lane >> 2, tig = lane & 3;
    const int wm = (warp & 3) * 32, wn = (warp >> 2) * 64;
#pragma unroll
    for (int tm = 0; tm < 2; tm++) {
        int r = m0 + wm + 16 * tm + g;
        int qc0 = g_qc[h * TT + r];
        int qc1 = g_qc[h * TT + r + 8];
#pragma unroll
        for (int tn = 0; tn < 8; tn++) {
            int c = n0 + wn + 8 * tn + 2 * tig;
            int kc0 = g_kc[h * TT + c];
            int kc1 = g_kc[h * TT + c + 1];
            float v00 = (c     <= r     && qc0 == kc0) ? acc[tm][tn][0] * scale : -1e30f;
            float v01 = (c + 1 <= r     && qc0 == kc1) ? acc[tm][tn][1] * scale : -1e30f;
            float v10 = (c     <= r + 8 && qc1 == kc0) ? acc[tm][tn][2] * scale : -1e30f;
            float v11 = (c + 1 <= r + 8 && qc1 == kc1) ? acc[tm][tn][3] * scale : -1e30f;
            *(float2*)(Sp + (size_t)r * TT + c) = make_float2(v00, v01);
            *(float2*)(Sp + (size_t)(r + 8) * TT + c) = make_float2(v10, v11);
        }
    }
}

// ---------------- P @ V ----------------
__global__ __launch_bounds__(256, 1) void k_pv_tc()
{
    const int h = blockIdx.z;
    const float* A = g_S + (size_t)h * TT * TT;   // weights [q][j], lda=T
    const float* B = g_Vt + (size_t)h * DD * TT;  // Vt [d][j], ldb=T
    float* C = g_Y + h * DD;                      // [q][h*128+d], ldc=C
    const int m0 = blockIdx.y * 128;
    const int kend = (blockIdx.y + 1) * 128;      // causal extent

    float acc[2][8][4];
    gemm_core(A, TT, B, TT, m0, 0, kend, acc);
    epi_store(C, CC, m0, 0, acc);
}

// ---------------- worklist counter zero ----------------
__global__ void k_zero_cnt() { g_fixcnt = 0; }

// ---------------- RoPE + RMS-norm + code + margin flagging ----------------
__global__ __launch_bounds__(256) void k_ropenorm(const float* __restrict__ cosb,
                                                  const float* __restrict__ sinb,
                                                  const float* __restrict__ Wdq,
                                                  const float* __restrict__ Wdk)
{
    int warp = (blockIdx.x * blockDim.x + threadIdx.x) >> 5;
    int lane = threadIdx.x & 31;
    int qk = warp >> 15;            // 0 = q, 1 = k
    int rem = warp & 32767;
    int t = rem >> 4;
    int h = rem & 15;

    const float* src = (qk ? g_Kraw : g_Qraw) + (size_t)t * CC + h * DD;
    const float* Wd = qk ? Wdk : Wdq;

    float v0 = src[lane], v1 = src[lane + 32], v2 = src[lane + 64], v3 = src[lane + 96];
    float c0 = cosb[t * 64 + lane],      s0 = sinb[t * 64 + lane];
    float c1 = cosb[t * 64 + lane + 32], s1 = sinb[t * 64 + lane + 32];

    float r0 =  v0 * c0 + v2 * s0;
    float r1 =  v1 * c1 + v3 * s1;
    float r2 = -v0 * s0 + v2 * c0;
    float r3 = -v1 * s1 + v3 * c1;

    float ss = r0 * r0 + r1 * r1 + r2 * r2 + r3 * r3;
#pragma unroll
    for (int o = 16; o; o >>= 1) ss += __shfl_xor_sync(0xffffffffu, ss, o);
    float sc = rsqrtf(ss * (1.0f / 128.0f) + 1e-6f);
    r0 *= sc; r1 *= sc; r2 *= sc; r3 *= sc;

    float* dst = (qk ? g_Kn : g_Qn) + ((size_t)h * TT + t) * DD;
    dst[lane] = r0; dst[lane + 32] = r1; dst[lane + 64] = r2; dst[lane + 96] = r3;

    int code = 0;
    float margin = 1e30f;
#pragma unroll
    for (int k = 0; k < NBITS; k++) {
        float z = r0 * Wd[k * DD + lane] + r1 * Wd[k * DD + lane + 32]
                + r2 * Wd[k * DD + lane + 64] + r3 * Wd[k * DD + lane + 96];
#pragma unroll
        for (int o = 16; o; o >>= 1) z += __shfl_xor_sync(0xffffffffu, z, o);
        float sg = 1.0f / (1.0f + expf(-z));
        float u = sg * 1.99f;
        int bit = (int)floorf(u);
        margin = fminf(margin, fabsf(u - 1.0f));
        code += bit << k;
    }
    if (lane == 0) {
        (qk ? g_kc : g_qc)[h * TT + t] = code;
        if (margin < 1e-3f) {
            int idx = atomicAdd(&g_fixcnt, 1);
            if (idx < FIXCAP) g_fixlist[idx] = (qk << 20) | (h << 16) | t;
        }
    }
}

// ---------------- exact FFMA recompute of flagged raw rows ----------------
// CRITICAL: single fp32 accumulator, fmaf over k ascending — the ordering that
// bitwise-matched the reference's code bits in rounds 2 and 5. Do NOT "improve"
// the precision here: the reference's own fp32 rounding is part of the target.
__global__ __launch_bounds__(128) void k_fix_raw(const float* __restrict__ x,
                                                 const float* __restrict__ Wq,
                                                 const float* __restrict__ Wk)
{
    int b = blockIdx.x;
    int cnt = g_fixcnt;
    if (cnt > FIXCAP) cnt = FIXCAP;
    if (b >= cnt) return;
    int e = g_fixlist[b];
    int qk = (e >> 20) & 1;
    int h = (e >> 16) & 15;
    int t = e & 0xFFFF;
    const float* W = qk ? Wk : Wq;
    float* dst = (qk ? g_Kraw : g_Qraw) + (size_t)t * CC + h * DD;
    int d = threadIdx.x;  // 0..127
    const float* xr = x + (size_t)t * CC;
    const float* wr = W + (size_t)(h * DD + d) * CC;
    float acc = 0.f;
    for (int k = 0; k < CC; k++) acc = fmaf(xr[k], wr[k], acc);
    dst[d] = acc;
}

// ---------------- rope/norm/code recompute for flagged rows only ----------------
__global__ __launch_bounds__(32) void k_rope_fix(const float* __restrict__ cosb,
                                                 const float* __restrict__ sinb,
                                                 const float* __restrict__ Wdq,
                                                 const float* __restrict__ Wdk)
{
    int b = blockIdx.x;
    int cnt = g_fixcnt;
    if (cnt > FIXCAP) cnt = FIXCAP;
    if (b >= cnt) return;
    int e = g_fixlist[b];
    int qk = (e >> 20) & 1;
    int h = (e >> 16) & 15;
    int t = e & 0xFFFF;
    int lane = threadIdx.x;

    const float* src = (qk ? g_Kraw : g_Qraw) + (size_t)t * CC + h * DD;
    const float* Wd = qk ? Wdk : Wdq;

    float v0 = src[lane], v1 = src[lane + 32], v2 = src[lane + 64], v3 = src[lane + 96];
    float c0 = cosb[t * 64 + lane],      s0 = sinb[t * 64 + lane];
    float c1 = cosb[t * 64 + lane + 32], s1 = sinb[t * 64 + lane + 32];

    float r0 =  v0 * c0 + v2 * s0;
    float r1 =  v1 * c1 + v3 * s1;
    float r2 = -v0 * s0 + v2 * c0;
    float r3 = -v1 * s1 + v3 * c1;

    float ss = r0 * r0 + r1 * r1 + r2 * r2 + r3 * r3;
#pragma unroll
    for (int o = 16; o; o >>= 1) ss += __shfl_xor_sync(0xffffffffu, ss, o);
    float sc = rsqrtf(ss * (1.0f / 128.0f) + 1e-6f);
    r0 *= sc; r1 *= sc; r2 *= sc; r3 *= sc;

    float* dst = (qk ? g_Kn : g_Qn) + ((size_t)h * TT + t) * DD;
    dst[lane] = r0; dst[lane + 32] = r1; dst[lane + 64] = r2; dst[lane + 96] = r3;

    int code = 0;
#pragma unroll
    for (int k = 0; k < NBITS; k++) {
        float z = r0 * Wd[k * DD + lane] + r1 * Wd[k * DD + lane + 32]
                + r2 * Wd[k * DD + lane + 64] + r3 * Wd[k * DD + lane + 96];
#pragma unroll
        for (int o = 16; o; o >>= 1) z += __shfl_xor_sync(0xffffffffu, z, o);
        float sg = 1.0f / (1.0f + expf(-z));
        int bit = (int)floorf(sg * 1.99f);
        code += bit << k;
    }
    if (lane == 0) (qk ? g_kc : g_qc)[h * TT + t] = code;
}

// ---------------- V transpose (2048x2048) ----------------
__global__ void k_transpose()
{
    __shared__ float tile[32][33];
    int x = blockIdx.x * 32 + threadIdx.x;
    int y = blockIdx.y * 32 + threadIdx.y;
#pragma unroll
    for (int i = 0; i < 32; i += 8)
        tile[threadIdx.y + i][threadIdx.x] = g_Vraw[(size_t)(y + i) * CC + x];
    __syncthreads();
    x = blockIdx.y * 32 + threadIdx.x;
    y = blockIdx.x * 32 + threadIdx.y;
#pragma unroll
    for (int i = 0; i < 32; i += 8)
        g_Vt[(size_t)(y + i) * TT + x] = tile[threadIdx.x][threadIdx.y + i];
}

// ---------------- row softmax (handles fully-masked rows -> zeros) ----------------
__global__ __launch_bounds__(128) void k_softmax()
{
    int row = blockIdx.x;          // h*T + q
    int h = row >> 11;
    int q = row & 2047;
    float* S = g_S + (size_t)h * TT * TT + (size_t)q * TT;
    int jmax = ((q >> 7) + 1) << 7;
    int tid = threadIdx.x;

    __shared__ float smax[4];
    __shared__ float ssum[4];

    float m = -1e30f;
    for (int j = tid; j < jmax; j += 128) m = fmaxf(m, S[j]);
#pragma unroll
    for (int o = 16; o; o >>= 1) m = fmaxf(m, __shfl_xor_sync(0xffffffffu, m, o));
    if ((tid & 31) == 0) smax[tid >> 5] = m;
    __syncthreads();
    m = fmaxf(fmaxf(smax[0], smax[1]), fmaxf(smax[2], smax[3]));

    if (m <= -1e29f) {
        for (int j = tid; j < jmax; j += 128) S[j] = 0.0f;
        return;
    }

    float e[16];
    float sum = 0.f;
    int cnt = 0;
    for (int j = tid; j < jmax; j += 128) {
        float v = expf(S[j] - m);
        e[cnt++] = v;
        sum += v;
    }
#pragma unroll
    for (int o = 16; o; o >>= 1) sum += __shfl_xor_sync(0xffffffffu, sum, o);
    if ((tid & 31) == 0) ssum[tid >> 5] = sum;
    __syncthreads();
    sum = ssum[0] + ssum[1] + ssum[2] + ssum[3];

    float inv = 1.0f / sum;
    cnt = 0;
    for (int j = tid; j < jmax; j += 128) S[j] = e[cnt++] * inv;
}

// ---------------- launch ----------------
extern "C" void kernel_launch(void* const* d_in, const int* in_sizes, int n_in,
                              void* d_out, int out_size)
{
    const float* x     = (const float*)d_in[0];
    const float* cosb  = (const float*)d_in[1];
    const float* sinb  = (const float*)d_in[2];
    const float* Wq    = (const float*)d_in[3];
    const float* Wk    = (const float*)d_in[4];
    const float* Wv    = (const float*)d_in[5];
    const float* Wproj = (const float*)d_in[6];
    const float* Wdq   = (const float*)d_in[7];
    const float* Wdk   = (const float*)d_in[8];
    float* out = (float*)d_out;

    k_zero_cnt<<<1, 1>>>();
    k_qkv_tc<<<dim3(16, 16, 3), 256>>>(x, Wq, Wk, Wv);

    // codes + margin flagging (all rows)
    k_ropenorm<<<(2 * TT * HH) / 8, 256>>>(cosb, sinb, Wdq, Wdk);
    // reference-ordering fp32 recompute of flagged raw rows, then their rope/codes
    k_fix_raw<<<FIXCAP, 128>>>(x, Wq, Wk);
    k_rope_fix<<<FIXCAP, 32>>>(cosb, sinb, Wdq, Wdk);

    k_transpose<<<dim3(64, 64), dim3(32, 8)>>>();

    k_scores_tc<<<dim3(16, 16, HH), 256>>>();
    k_softmax<<<HH * TT, 128>>>();
    k_pv_tc<<<dim3(1, 16, HH), 256>>>();

    k_proj_tc<<<dim3(16, 16, 1), 256>>>(Wproj, out);
}

// round 8
// speedup vs baseline: 1.3606x; 1.3606x over previous
#include <cuda_runtime.h>
#include <cuda_bf16.h>
#include <math.h>
#include <stdint.h>

#define TT 2048          // sequence length
#define CC 2048          // embed dim
#define HH 16            // heads
#define DD 128           // head dim
#define NBITS 7
#define BKH 16           // k-slab for bf16x3 core
#define RSW 12           // u32 words per row per split tile (8 used + 4 pad)
#define FIXCAP 8192

// ---------------- scratch (static device globals; no allocation) ----------------
__device__ float g_Qraw[(size_t)TT * CC];
__device__ float g_Kraw[(size_t)TT * CC];
__device__ float g_Vraw[(size_t)TT * CC];
__device__ float g_Qn[(size_t)HH * TT * DD];   // [h][t][d] rope+rmsnorm
__device__ float g_Kn[(size_t)HH * TT * DD];
__device__ float g_Vt[(size_t)CC * TT];        // Vraw transposed: [h*128+d][t]
__device__ float g_S[(size_t)HH * TT * TT];    // scores -> softmax weights
__device__ float g_Y[(size_t)TT * CC];         // attention output, [t][h*128+d]
__device__ int   g_qc[HH * TT];
__device__ int   g_kc[HH * TT];
__device__ int   g_fixcnt;
__device__ int   g_fixlist[FIXCAP];

// ============================================================
// bf16x3 emulated-fp32 GEMM core (all GEMMs)
// ============================================================
__device__ __forceinline__ void split2(float x, float& hi, float& lo)
{
    hi = __bfloat162float(__float2bfloat16_rn(x));
    lo = x - hi;
}

__device__ __forceinline__ uint32_t pack2(float a, float b)
{
    __nv_bfloat162 t = __floats2bfloat162_rn(a, b);   // a -> low half
    return *reinterpret_cast<uint32_t*>(&t);
}

__device__ __forceinline__ void mma_bf16(float d[4], const uint32_t a[4],
                                         uint32_t b0, uint32_t b1)
{
    asm volatile(
        "mma.sync.aligned.m16n8k16.row.col.f32.bf16.bf16.f32 "
        "{%0,%1,%2,%3}, {%4,%5,%6,%7}, {%8,%9}, {%0,%1,%2,%3};"
        : "+f"(d[0]), "+f"(d[1]), "+f"(d[2]), "+f"(d[3])
        : "r"(a[0]), "r"(a[1]), "r"(a[2]), "r"(a[3]), "r"(b0), "r"(b1));
}

// C = A(m0+128 x kend) . B^T; A row-major lda, B row-major ldb. kend % 16 == 0.
__device__ __forceinline__ void gemm_core(const float* __restrict__ A, int lda,
                                          const float* __restrict__ B, int ldb,
                                          int m0, int n0, int kend,
                                          float acc[2][8][4])
{
    __shared__ uint32_t sA[2][128 * RSW];
    __shared__ uint32_t sB[2][128 * RSW];

    const int tid = threadIdx.x, lane = tid & 31, warp = tid >> 5;
    const int g = lane >> 2, tig = lane & 3;
    const int wm = (warp & 3) * 32, wn = (warp >> 2) * 64;

#pragma unroll
    for (int tm = 0; tm < 2; tm++)
#pragma unroll
        for (int tn = 0; tn < 8; tn++)
#pragma unroll
            for (int e = 0; e < 4; e++) acc[tm][tn][e] = 0.f;

    // producer mapping: slot = tid + 256*i -> row m = slot>>2, float4 j = slot&3
    float4 pa[2], pb[2];
#pragma unroll
    for (int i = 0; i < 2; i++) {
        int slot = tid + 256 * i, m = slot >> 2, j = slot & 3;
        pa[i] = *(const float4*)(A + (size_t)(m0 + m) * lda + 4 * j);
        pb[i] = *(const float4*)(B + (size_t)(n0 + m) * ldb + 4 * j);
    }

    for (int k0 = 0; k0 < kend; k0 += BKH) {
#pragma unroll
        for (int i = 0; i < 2; i++) {
            int slot = tid + 256 * i, m = slot >> 2, j = slot & 3;
            float h0, l0, h1, l1, h2, l2, h3, l3;
            split2(pa[i].x, h0, l0); split2(pa[i].y, h1, l1);
            split2(pa[i].z, h2, l2); split2(pa[i].w, h3, l3);
            sA[0][m * RSW + 2 * j]     = pack2(h0, h1);
            sA[0][m * RSW + 2 * j + 1] = pack2(h2, h3);
            sA[1][m * RSW + 2 * j]     = pack2(l0, l1);
            sA[1][m * RSW + 2 * j + 1] = pack2(l2, l3);
            split2(pb[i].x, h0, l0); split2(pb[i].y, h1, l1);
            split2(pb[i].z, h2, l2); split2(pb[i].w, h3, l3);
            sB[0][m * RSW + 2 * j]     = pack2(h0, h1);
            sB[0][m * RSW + 2 * j + 1] = pack2(h2, h3);
            sB[1][m * RSW + 2 * j]     = pack2(l0, l1);
            sB[1][m * RSW + 2 * j + 1] = pack2(l2, l3);
        }
        __syncthreads();

        if (k0 + BKH < kend) {
#pragma unroll
            for (int i = 0; i < 2; i++) {
                int slot = tid + 256 * i, m = slot >> 2, j = slot & 3;
                pa[i] = *(const float4*)(A + (size_t)(m0 + m) * lda + k0 + BKH + 4 * j);
                pb[i] = *(const float4*)(B + (size_t)(n0 + m) * ldb + k0 + BKH + 4 * j);
            }
        }

        uint32_t ar[2][2][4];
#pragma unroll
        for (int s = 0; s < 2; s++)
#pragma unroll
            for (int tm = 0; tm < 2; tm++) {
                int r = wm + 16 * tm + g;
                ar[s][tm][0] = sA[s][r * RSW + tig];
                ar[s][tm][1] = sA[s][(r + 8) * RSW + tig];
                ar[s][tm][2] = sA[s][r * RSW + tig + 4];
                ar[s][tm][3] = sA[s][(r + 8) * RSW + tig + 4];
            }

#pragma unroll
        for (int tn = 0; tn < 8; tn++) {
            int c = wn + 8 * tn + g;
            uint32_t bh0 = sB[0][c * RSW + tig];
            uint32_t bh1 = sB[0][c * RSW + tig + 4];
            uint32_t bl0 = sB[1][c * RSW + tig];
            uint32_t bl1 = sB[1][c * RSW + tig + 4];
#pragma unroll
            for (int tm = 0; tm < 2; tm++) {
                mma_bf16(acc[tm][tn], ar[1][tm], bh0, bh1);  // lo*hi
                mma_bf16(acc[tm][tn], ar[0][tm], bl0, bl1);  // hi*lo
                mma_bf16(acc[tm][tn], ar[0][tm], bh0, bh1);  // hi*hi
            }
        }
        __syncthreads();
    }
}

__device__ __forceinline__ void epi_store(float* __restrict__ C, int ldc,
                                          int m0, int n0, float acc[2][8][4])
{
    const int lane = threadIdx.x & 31, warp = threadIdx.x >> 5;
    const int g = lane >> 2, tig = lane & 3;
    const int wm = (warp & 3) * 32, wn = (warp >> 2) * 64;
#pragma unroll
    for (int tm = 0; tm < 2; tm++)
#pragma unroll
        for (int tn = 0; tn < 8; tn++) {
            int r = m0 + wm + 16 * tm + g;
            int c = n0 + wn + 8 * tn + 2 * tig;
            *(float2*)(C + (size_t)r * ldc + c) = make_float2(acc[tm][tn][0], acc[tm][tn][1]);
            *(float2*)(C + (size_t)(r + 8) * ldc + c) = make_float2(acc[tm][tn][2], acc[tm][tn][3]);
        }
}

// ---------------- QKV projections ----------------
__global__ __launch_bounds__(256, 1) void k_qkv_tc(const float* __restrict__ x,
                                                   const float* __restrict__ Wq,
                                                   const float* __restrict__ Wk,
                                                   const float* __restrict__ Wv)
{
    const float* B = (blockIdx.z == 0) ? Wq : (blockIdx.z == 1) ? Wk : Wv;
    float* C = (blockIdx.z == 0) ? g_Qraw : (blockIdx.z == 1) ? g_Kraw : g_Vraw;
    float acc[2][8][4];
    gemm_core(x, CC, B, CC, blockIdx.y * 128, blockIdx.x * 128, CC, acc);
    epi_store(C, CC, blockIdx.y * 128, blockIdx.x * 128, acc);
}

// ---------------- output projection ----------------
__global__ __launch_bounds__(256, 1) void k_proj_tc(const float* __restrict__ Wproj,
                                                    float* __restrict__ out)
{
    float acc[2][8][4];
    gemm_core(g_Y, CC, Wproj, CC, blockIdx.y * 128, blockIdx.x * 128, CC, acc);
    epi_store(out, CC, blockIdx.y * 128, blockIdx.x * 128, acc);
}

// ---------------- masked scores ----------------
__global__ __launch_bounds__(256, 1) void k_scores_tc()
{
    if (blockIdx.x > blockIdx.y) return;   // upper-triangular blocks never read
    const int h = blockIdx.z;
    const float* A = g_Qn + (size_t)h * TT * DD;
    const float* B = g_Kn + (size_t)h * TT * DD;
    float* Sp = g_S + (size_t)h * TT * TT;
    const int m0 = blockIdx.y * 128, n0 = blockIdx.x * 128;

    float acc[2][8][4];
    gemm_core(A, DD, B, DD, m0, n0, DD, acc);

    const float scale = 0.08838834764831845f;  // 1/sqrt(128)
    const int lane = threadIdx.x & 31, warp = threadIdx.x >> 5;
    const int g = lane >> 2, tig = lane & 3;
    const int wm = (warp & 3) * 32, wn = (warp >> 2) * 64;
#pragma unroll
    for (int tm = 0; tm < 2; tm++) {
        int r = m0 + wm + 16 * tm + g;
        int qc0 = g_qc[h * TT + r];
        int qc1 = g_qc[h * TT + r + 8];
#pragma unroll
        for (int tn = 0; tn < 8; tn++) {
            int c = n0 + wn + 8 * tn + 2 * tig;
            int kc0 = g_kc[h * TT + c];
            int kc1 = g_kc[h * TT + c + 1];
            float v00 = (c     <= r     && qc0 == kc0) ? acc[tm][tn][0] * scale : -1e30f;
            float v01 = (c + 1 <= r     && qc0 == kc1) ? acc[tm][tn][1] * scale : -1e30f;
            float v10 = (c     <= r + 8 && qc1 == kc0) ? acc[tm][tn][2] * scale : -1e30f;
            float v11 = (c + 1 <= r + 8 && qc1 == kc1) ? acc[tm][tn][3] * scale : -1e30f;
            *(float2*)(Sp + (size_t)r * TT + c) = make_float2(v00, v01);
            *(float2*)(Sp + (size_t)(r + 8) * TT + c) = make_float2(v10, v11);
        }
    }
}

// ---------------- P @ V ----------------
__global__ __launch_bounds__(256, 1) void k_pv_tc()
{
    const int h = blockIdx.z;
    const float* A = g_S + (size_t)h * TT * TT;   // weights [q][j], lda=T
    const float* B = g_Vt + (size_t)h * DD * TT;  // Vt [d][j], ldb=T
    float* C = g_Y + h * DD;                      // [q][h*128+d], ldc=C
    const int m0 = blockIdx.y * 128;
    const int kend = (blockIdx.y + 1) * 128;      // causal extent

    float acc[2][8][4];
    gemm_core(A, TT, B, TT, m0, 0, kend, acc);
    epi_store(C, CC, m0, 0, acc);
}

// ---------------- worklist counter zero ----------------
__global__ void k_zero_cnt() { g_fixcnt = 0; }

// ---------------- RoPE + RMS-norm + code + margin flagging ----------------
__global__ __launch_bounds__(256) void k_ropenorm(const float* __restrict__ cosb,
                                                  const float* __restrict__ sinb,
                                                  const float* __restrict__ Wdq,
                                                  const float* __restrict__ Wdk)
{
    int warp = (blockIdx.x * blockDim.x + threadIdx.x) >> 5;
    int lane = threadIdx.x & 31;
    int qk = warp >> 15;            // 0 = q, 1 = k
    int rem = warp & 32767;
    int t = rem >> 4;
    int h = rem & 15;

    const float* src = (qk ? g_Kraw : g_Qraw) + (size_t)t * CC + h * DD;
    const float* Wd = qk ? Wdk : Wdq;

    float v0 = src[lane], v1 = src[lane + 32], v2 = src[lane + 64], v3 = src[lane + 96];
    float c0 = cosb[t * 64 + lane],      s0 = sinb[t * 64 + lane];
    float c1 = cosb[t * 64 + lane + 32], s1 = sinb[t * 64 + lane + 32];

    float r0 =  v0 * c0 + v2 * s0;
    float r1 =  v1 * c1 + v3 * s1;
    float r2 = -v0 * s0 + v2 * c0;
    float r3 = -v1 * s1 + v3 * c1;

    float ss = r0 * r0 + r1 * r1 + r2 * r2 + r3 * r3;
#pragma unroll
    for (int o = 16; o; o >>= 1) ss += __shfl_xor_sync(0xffffffffu, ss, o);
    float sc = rsqrtf(ss * (1.0f / 128.0f) + 1e-6f);
    r0 *= sc; r1 *= sc; r2 *= sc; r3 *= sc;

    float* dst = (qk ? g_Kn : g_Qn) + ((size_t)h * TT + t) * DD;
    dst[lane] = r0; dst[lane + 32] = r1; dst[lane + 64] = r2; dst[lane + 96] = r3;

    int code = 0;
    float margin = 1e30f;
#pragma unroll
    for (int k = 0; k < NBITS; k++) {
        float z = r0 * Wd[k * DD + lane] + r1 * Wd[k * DD + lane + 32]
                + r2 * Wd[k * DD + lane + 64] + r3 * Wd[k * DD + lane + 96];
#pragma unroll
        for (int o = 16; o; o >>= 1) z += __shfl_xor_sync(0xffffffffu, z, o);
        float sg = 1.0f / (1.0f + expf(-z));
        float u = sg * 1.99f;
        int bit = (int)floorf(u);
        margin = fminf(margin, fabsf(u - 1.0f));
        code += bit << k;
    }
    if (lane == 0) {
        (qk ? g_kc : g_qc)[h * TT + t] = code;
        if (margin < 1e-3f) {
            int idx = atomicAdd(&g_fixcnt, 1);
            if (idx < FIXCAP) g_fixlist[idx] = (qk << 20) | (h << 16) | t;
        }
    }
}

// ---------------- exact FFMA recompute of flagged raw rows ----------------
// CRITICAL: per output element, single fp32 accumulator, fma over k ascending —
// the ordering that matched the reference's code bits (rounds 2/5/7). Only the
// MEMORY ACCESS pattern is optimized here: x row staged in smem (coalesced),
// W read as float4 with one-iteration prefetch so loads leave the fma chain.
__global__ __launch_bounds__(128) void k_fix_raw(const float* __restrict__ x,
                                                 const float* __restrict__ Wq,
                                                 const float* __restrict__ Wk)
{
    __shared__ float4 sx[CC / 4];
    int b = blockIdx.x;
    int cnt = g_fixcnt;
    if (cnt > FIXCAP) cnt = FIXCAP;
    if (b >= cnt) return;
    int e = g_fixlist[b];
    int qk = (e >> 20) & 1;
    int h = (e >> 16) & 15;
    int t = e & 0xFFFF;

    // stage shared x row (coalesced: 128 threads x 4 float4)
    const float4* xr4 = (const float4*)(x + (size_t)t * CC);
#pragma unroll
    for (int i = 0; i < 4; i++) sx[threadIdx.x + 128 * i] = xr4[threadIdx.x + 128 * i];
    __syncthreads();

    const float* W = qk ? Wk : Wq;
    float* dst = (qk ? g_Kraw : g_Qraw) + (size_t)t * CC + h * DD;
    int d = threadIdx.x;  // 0..127
    const float4* wr4 = (const float4*)(W + (size_t)(h * DD + d) * CC);

    float acc = 0.f;
    float4 w = wr4[0];
#pragma unroll 4
    for (int k4 = 0; k4 < CC / 4; k4++) {
        float4 wn = (k4 + 1 < CC / 4) ? wr4[k4 + 1] : w;   // prefetch next
        float4 xx = sx[k4];
        acc = fmaf(xx.x, w.x, acc);
        acc = fmaf(xx.y, w.y, acc);
        acc = fmaf(xx.z, w.z, acc);
        acc = fmaf(xx.w, w.w, acc);
        w = wn;
    }
    dst[d] = acc;
}

// ---------------- rope/norm/code recompute for flagged rows only ----------------
__global__ __launch_bounds__(32) void k_rope_fix(const float* __restrict__ cosb,
                                                 const float* __restrict__ sinb,
                                                 const float* __restrict__ Wdq,
                                                 const float* __restrict__ Wdk)
{
    int b = blockIdx.x;
    int cnt = g_fixcnt;
    if (cnt > FIXCAP) cnt = FIXCAP;
    if (b >= cnt) return;
    int e = g_fixlist[b];
    int qk = (e >> 20) & 1;
    int h = (e >> 16) & 15;
    int t = e & 0xFFFF;
    int lane = threadIdx.x;

    const float* src = (qk ? g_Kraw : g_Qraw) + (size_t)t * CC + h * DD;
    const float* Wd = qk ? Wdk : Wdq;

    float v0 = src[lane], v1 = src[lane + 32], v2 = src[lane + 64], v3 = src[lane + 96];
    float c0 = cosb[t * 64 + lane],      s0 = sinb[t * 64 + lane];
    float c1 = cosb[t * 64 + lane + 32], s1 = sinb[t * 64 + lane + 32];

    float r0 =  v0 * c0 + v2 * s0;
    float r1 =  v1 * c1 + v3 * s1;
    float r2 = -v0 * s0 + v2 * c0;
    float r3 = -v1 * s1 + v3 * c1;

    float ss = r0 * r0 + r1 * r1 + r2 * r2 + r3 * r3;
#pragma unroll
    for (int o = 16; o; o >>= 1) ss += __shfl_xor_sync(0xffffffffu, ss, o);
    float sc = rsqrtf(ss * (1.0f / 128.0f) + 1e-6f);
    r0 *= sc; r1 *= sc; r2 *= sc; r3 *= sc;

    float* dst = (qk ? g_Kn : g_Qn) + ((size_t)h * TT + t) * DD;
    dst[lane] = r0; dst[lane + 32] = r1; dst[lane + 64] = r2; dst[lane + 96] = r3;

    int code = 0;
#pragma unroll
    for (int k = 0; k < NBITS; k++) {
        float z = r0 * Wd[k * DD + lane] + r1 * Wd[k * DD + lane + 32]
                + r2 * Wd[k * DD + lane + 64] + r3 * Wd[k * DD + lane + 96];
#pragma unroll
        for (int o = 16; o; o >>= 1) z += __shfl_xor_sync(0xffffffffu, z, o);
        float sg = 1.0f / (1.0f + expf(-z));
        int bit = (int)floorf(sg * 1.99f);
        code += bit << k;
    }
    if (lane == 0) (qk ? g_kc : g_qc)[h * TT + t] = code;
}

// ---------------- V transpose (2048x2048) ----------------
__global__ void k_transpose()
{
    __shared__ float tile[32][33];
    int x = blockIdx.x * 32 + threadIdx.x;
    int y = blockIdx.y * 32 + threadIdx.y;
#pragma unroll
    for (int i = 0; i < 32; i += 8)
        tile[threadIdx.y + i][threadIdx.x] = g_Vraw[(size_t)(y + i) * CC + x];
    __syncthreads();
    x = blockIdx.y * 32 + threadIdx.x;
    y = blockIdx.x * 32 + threadIdx.y;
#pragma unroll
    for (int i = 0; i < 32; i += 8)
        g_Vt[(size_t)(y + i) * TT + x] = tile[threadIdx.x][threadIdx.y + i];
}

// ---------------- row softmax (handles fully-masked rows -> zeros) ----------------
__global__ __launch_bounds__(128) void k_softmax()
{
    int row = blockIdx.x;          // h*T + q
    int h = row >> 11;
    int q = row & 2047;
    float* S = g_S + (size_t)h * TT * TT + (size_t)q * TT;
    int jmax = ((q >> 7) + 1) << 7;
    int tid = threadIdx.x;

    __shared__ float smax[4];
    __shared__ float ssum[4];

    float m = -1e30f;
    for (int j = tid; j < jmax; j += 128) m = fmaxf(m, S[j]);
#pragma unroll
    for (int o = 16; o; o >>= 1) m = fmaxf(m, __shfl_xor_sync(0xffffffffu, m, o));
    if ((tid & 31) == 0) smax[tid >> 5] = m;
    __syncthreads();
    m = fmaxf(fmaxf(smax[0], smax[1]), fmaxf(smax[2], smax[3]));

    if (m <= -1e29f) {
        for (int j = tid; j < jmax; j += 128) S[j] = 0.0f;
        return;
    }

    float e[16];
    float sum = 0.f;
    int cnt = 0;
    for (int j = tid; j < jmax; j += 128) {
        float v = expf(S[j] - m);
        e[cnt++] = v;
        sum += v;
    }
#pragma unroll
    for (int o = 16; o; o >>= 1) sum += __shfl_xor_sync(0xffffffffu, sum, o);
    if ((tid & 31) == 0) ssum[tid >> 5] = sum;
    __syncthreads();
    sum = ssum[0] + ssum[1] + ssum[2] + ssum[3];

    float inv = 1.0f / sum;
    cnt = 0;
    for (int j = tid; j < jmax; j += 128) S[j] = e[cnt++] * inv;
}

// ---------------- launch ----------------
extern "C" void kernel_launch(void* const* d_in, const int* in_sizes, int n_in,
                              void* d_out, int out_size)
{
    const float* x     = (const float*)d_in[0];
    const float* cosb  = (const float*)d_in[1];
    const float* sinb  = (const float*)d_in[2];
    const float* Wq    = (const float*)d_in[3];
    const float* Wk    = (const float*)d_in[4];
    const float* Wv    = (const float*)d_in[5];
    const float* Wproj = (const float*)d_in[6];
    const float* Wdq   = (const float*)d_in[7];
    const float* Wdk   = (const float*)d_in[8];
    float* out = (float*)d_out;

    k_zero_cnt<<<1, 1>>>();
    k_qkv_tc<<<dim3(16, 16, 3), 256>>>(x, Wq, Wk, Wv);

    // codes + margin flagging (all rows)
    k_ropenorm<<<(2 * TT * HH) / 8, 256>>>(cosb, sinb, Wdq, Wdk);
    // reference-ordering fp32 recompute of flagged raw rows, then their rope/codes
    k_fix_raw<<<FIXCAP, 128>>>(x, Wq, Wk);
    k_rope_fix<<<FIXCAP, 32>>>(cosb, sinb, Wdq, Wdk);

    k_transpose<<<dim3(64, 64), dim3(32, 8)>>>();

    k_scores_tc<<<dim3(16, 16, HH), 256>>>();
    k_softmax<<<HH * TT, 128>>>();
    k_pv_tc<<<dim3(1, 16, HH), 256>>>();

    k_proj_tc<<<dim3(16, 16, 1), 256>>>(Wproj, out);
}

// round 9
// speedup vs baseline: 1.4977x; 1.1008x over previous
#include <cuda_runtime.h>
#include <cuda_bf16.h>
#include <math.h>
#include <stdint.h>

#define TT 2048          // sequence length
#define CC 2048          // embed dim
#define HH 16            // heads
#define DD 128           // head dim
#define NBITS 7
#define BKH 16           // k-slab for bf16x3 core
#define RSW 12           // u32 words per row per split tile (8 used + 4 pad)
#define FIXCAP 8192
#define KT 64            // k-tile for k_fix_raw W staging

// ---------------- scratch (static device globals; no allocation) ----------------
__device__ float g_Qraw[(size_t)TT * CC];
__device__ float g_Kraw[(size_t)TT * CC];
__device__ float g_Vraw[(size_t)TT * CC];
__device__ float g_Qn[(size_t)HH * TT * DD];   // [h][t][d] rope+rmsnorm
__device__ float g_Kn[(size_t)HH * TT * DD];
__device__ float g_Vt[(size_t)CC * TT];        // Vraw transposed: [h*128+d][t]
__device__ float g_S[(size_t)HH * TT * TT];    // scores -> softmax weights
__device__ float g_Y[(size_t)TT * CC];         // attention output, [t][h*128+d]
__device__ int   g_qc[HH * TT];
__device__ int   g_kc[HH * TT];
__device__ int   g_fixcnt;
__device__ int   g_fixlist[FIXCAP];

// ============================================================
// bf16x3 emulated-fp32 GEMM core (all GEMMs)
// ============================================================
__device__ __forceinline__ void split2(float x, float& hi, float& lo)
{
    hi = __bfloat162float(__float2bfloat16_rn(x));
    lo = x - hi;
}

__device__ __forceinline__ uint32_t pack2(float a, float b)
{
    __nv_bfloat162 t = __floats2bfloat162_rn(a, b);   // a -> low half
    return *reinterpret_cast<uint32_t*>(&t);
}

__device__ __forceinline__ void mma_bf16(float d[4], const uint32_t a[4],
                                         uint32_t b0, uint32_t b1)
{
    asm volatile(
        "mma.sync.aligned.m16n8k16.row.col.f32.bf16.bf16.f32 "
        "{%0,%1,%2,%3}, {%4,%5,%6,%7}, {%8,%9}, {%0,%1,%2,%3};"
        : "+f"(d[0]), "+f"(d[1]), "+f"(d[2]), "+f"(d[3])
        : "r"(a[0]), "r"(a[1]), "r"(a[2]), "r"(a[3]), "r"(b0), "r"(b1));
}

// C = A(m0+128 x kend) . B^T; A row-major lda, B row-major ldb. kend % 16 == 0.
__device__ __forceinline__ void gemm_core(const float* __restrict__ A, int lda,
                                          const float* __restrict__ B, int ldb,
                                          int m0, int n0, int kend,
                                          float acc[2][8][4])
{
    __shared__ uint32_t sA[2][128 * RSW];
    __shared__ uint32_t sB[2][128 * RSW];

    const int tid = threadIdx.x, lane = tid & 31, warp = tid >> 5;
    const int g = lane >> 2, tig = lane & 3;
    const int wm = (warp & 3) * 32, wn = (warp >> 2) * 64;

#pragma unroll
    for (int tm = 0; tm < 2; tm++)
#pragma unroll
        for (int tn = 0; tn < 8; tn++)
#pragma unroll
            for (int e = 0; e < 4; e++) acc[tm][tn][e] = 0.f;

    // producer mapping: slot = tid + 256*i -> row m = slot>>2, float4 j = slot&3
    float4 pa[2], pb[2];
#pragma unroll
    for (int i = 0; i < 2; i++) {
        int slot = tid + 256 * i, m = slot >> 2, j = slot & 3;
        pa[i] = *(const float4*)(A + (size_t)(m0 + m) * lda + 4 * j);
        pb[i] = *(const float4*)(B + (size_t)(n0 + m) * ldb + 4 * j);
    }

    for (int k0 = 0; k0 < kend; k0 += BKH) {
#pragma unroll
        for (int i = 0; i < 2; i++) {
            int slot = tid + 256 * i, m = slot >> 2, j = slot & 3;
            float h0, l0, h1, l1, h2, l2, h3, l3;
            split2(pa[i].x, h0, l0); split2(pa[i].y, h1, l1);
            split2(pa[i].z, h2, l2); split2(pa[i].w, h3, l3);
            sA[0][m * RSW + 2 * j]     = pack2(h0, h1);
            sA[0][m * RSW + 2 * j + 1] = pack2(h2, h3);
            sA[1][m * RSW + 2 * j]     = pack2(l0, l1);
            sA[1][m * RSW + 2 * j + 1] = pack2(l2, l3);
            split2(pb[i].x, h0, l0); split2(pb[i].y, h1, l1);
            split2(pb[i].z, h2, l2); split2(pb[i].w, h3, l3);
            sB[0][m * RSW + 2 * j]     = pack2(h0, h1);
            sB[0][m * RSW + 2 * j + 1] = pack2(h2, h3);
            sB[1][m * RSW + 2 * j]     = pack2(l0, l1);
            sB[1][m * RSW + 2 * j + 1] = pack2(l2, l3);
        }
        __syncthreads();

        if (k0 + BKH < kend) {
#pragma unroll
            for (int i = 0; i < 2; i++) {
                int slot = tid + 256 * i, m = slot >> 2, j = slot & 3;
                pa[i] = *(const float4*)(A + (size_t)(m0 + m) * lda + k0 + BKH + 4 * j);
                pb[i] = *(const float4*)(B + (size_t)(n0 + m) * ldb + k0 + BKH + 4 * j);
            }
        }

        uint32_t ar[2][2][4];
#pragma unroll
        for (int s = 0; s < 2; s++)
#pragma unroll
            for (int tm = 0; tm < 2; tm++) {
                int r = wm + 16 * tm + g;
                ar[s][tm][0] = sA[s][r * RSW + tig];
                ar[s][tm][1] = sA[s][(r + 8) * RSW + tig];
                ar[s][tm][2] = sA[s][r * RSW + tig + 4];
                ar[s][tm][3] = sA[s][(r + 8) * RSW + tig + 4];
            }

#pragma unroll
        for (int tn = 0; tn < 8; tn++) {
            int c = wn + 8 * tn + g;
            uint32_t bh0 = sB[0][c * RSW + tig];
            uint32_t bh1 = sB[0][c * RSW + tig + 4];
            uint32_t bl0 = sB[1][c * RSW + tig];
            uint32_t bl1 = sB[1][c * RSW + tig + 4];
#pragma unroll
            for (int tm = 0; tm < 2; tm++) {
                mma_bf16(acc[tm][tn], ar[1][tm], bh0, bh1);  // lo*hi
                mma_bf16(acc[tm][tn], ar[0][tm], bl0, bl1);  // hi*lo
                mma_bf16(acc[tm][tn], ar[0][tm], bh0, bh1);  // hi*hi
            }
        }
        __syncthreads();
    }
}

__device__ __forceinline__ void epi_store(float* __restrict__ C, int ldc,
                                          int m0, int n0, float acc[2][8][4])
{
    const int lane = threadIdx.x & 31, warp = threadIdx.x >> 5;
    const int g = lane >> 2, tig = lane & 3;
    const int wm = (warp & 3) * 32, wn = (warp >> 2) * 64;
#pragma unroll
    for (int tm = 0; tm < 2; tm++)
#pragma unroll
        for (int tn = 0; tn < 8; tn++) {
            int r = m0 + wm + 16 * tm + g;
            int c = n0 + wn + 8 * tn + 2 * tig;
            *(float2*)(C + (size_t)r * ldc + c) = make_float2(acc[tm][tn][0], acc[tm][tn][1]);
            *(float2*)(C + (size_t)(r + 8) * ldc + c) = make_float2(acc[tm][tn][2], acc[tm][tn][3]);
        }
}

// ---------------- QKV projections ----------------
__global__ __launch_bounds__(256, 1) void k_qkv_tc(const float* __restrict__ x,
                                                   const float* __restrict__ Wq,
                                                   const float* __restrict__ Wk,
                                                   const float* __restrict__ Wv)
{
    const float* B = (blockIdx.z == 0) ? Wq : (blockIdx.z == 1) ? Wk : Wv;
    float* C = (blockIdx.z == 0) ? g_Qraw : (blockIdx.z == 1) ? g_Kraw : g_Vraw;
    float acc[2][8][4];
    gemm_core(x, CC, B, CC, blockIdx.y * 128, blockIdx.x * 128, CC, acc);
    epi_store(C, CC, blockIdx.y * 128, blockIdx.x * 128, acc);
}

// ---------------- output projection ----------------
__global__ __launch_bounds__(256, 1) void k_proj_tc(const float* __restrict__ Wproj,
                                                    float* __restrict__ out)
{
    float acc[2][8][4];
    gemm_core(g_Y, CC, Wproj, CC, blockIdx.y * 128, blockIdx.x * 128, CC, acc);
    epi_store(out, CC, blockIdx.y * 128, blockIdx.x * 128, acc);
}

// ---------------- masked scores ----------------
__global__ __launch_bounds__(256, 1) void k_scores_tc()
{
    if (blockIdx.x > blockIdx.y) return;   // upper-triangular blocks never read
    const int h = blockIdx.z;
    const float* A = g_Qn + (size_t)h * TT * DD;
    const float* B = g_Kn + (size_t)h * TT * DD;
    float* Sp = g_S + (size_t)h * TT * TT;
    const int m0 = blockIdx.y * 128, n0 = blockIdx.x * 128;

    float acc[2][8][4];
    gemm_core(A, DD, B, DD, m0, n0, DD, acc);

    const float scale = 0.08838834764831845f;  // 1/sqrt(128)
    const int lane = threadIdx.x & 31, warp = threadIdx.x >> 5;
    const int g = lane >> 2, tig = lane & 3;
    const int wm = (warp & 3) * 32, wn = (warp >> 2) * 64;
#pragma unroll
    for (int tm = 0; tm < 2; tm++) {
        int r = m0 + wm + 16 * tm + g;
        int qc0 = g_qc[h * TT + r];
        int qc1 = g_qc[h * TT + r + 8];
#pragma unroll
        for (int tn = 0; tn < 8; tn++) {
            int c = n0 + wn + 8 * tn + 2 * tig;
            int kc0 = g_kc[h * TT + c];
            int kc1 = g_kc[h * TT + c + 1];
            float v00 = (c     <= r     && qc0 == kc0) ? acc[tm][tn][0] * scale : -1e30f;
            float v01 = (c + 1 <= r     && qc0 == kc1) ? acc[tm][tn][1] * scale : -1e30f;
            float v10 = (c     <= r + 8 && qc1 == kc0) ? acc[tm][tn][2] * scale : -1e30f;
            float v11 = (c + 1 <= r + 8 && qc1 == kc1) ? acc[tm][tn][3] * scale : -1e30f;
            *(float2*)(Sp + (size_t)r * TT + c) = make_float2(v00, v01);
            *(float2*)(Sp + (size_t)(r + 8) * TT + c) = make_float2(v10, v11);
        }
    }
}

// ---------------- P @ V ----------------
__global__ __launch_bounds__(256, 1) void k_pv_tc()
{
    const int h = blockIdx.z;
    const float* A = g_S + (size_t)h * TT * TT;   // weights [q][j], lda=T
    const float* B = g_Vt + (size_t)h * DD * TT;  // Vt [d][j], ldb=T
    float* C = g_Y + h * DD;                      // [q][h*128+d], ldc=C
    const int m0 = blockIdx.y * 128;
    const int kend = (blockIdx.y + 1) * 128;      // causal extent

    float acc[2][8][4];
    gemm_core(A, TT, B, TT, m0, 0, kend, acc);
    epi_store(C, CC, m0, 0, acc);
}

// ---------------- worklist counter zero ----------------
__global__ void k_zero_cnt() { g_fixcnt = 0; }

// ---------------- RoPE + RMS-norm + code + margin flagging ----------------
__global__ __launch_bounds__(256) void k_ropenorm(const float* __restrict__ cosb,
                                                  const float* __restrict__ sinb,
                                                  const float* __restrict__ Wdq,
                                                  const float* __restrict__ Wdk)
{
    int warp = (blockIdx.x * blockDim.x + threadIdx.x) >> 5;
    int lane = threadIdx.x & 31;
    int qk = warp >> 15;            // 0 = q, 1 = k
    int rem = warp & 32767;
    int t = rem >> 4;
    int h = rem & 15;

    const float* src = (qk ? g_Kraw : g_Qraw) + (size_t)t * CC + h * DD;
    const float* Wd = qk ? Wdk : Wdq;

    float v0 = src[lane], v1 = src[lane + 32], v2 = src[lane + 64], v3 = src[lane + 96];
    float c0 = cosb[t * 64 + lane],      s0 = sinb[t * 64 + lane];
    float c1 = cosb[t * 64 + lane + 32], s1 = sinb[t * 64 + lane + 32];

    float r0 =  v0 * c0 + v2 * s0;
    float r1 =  v1 * c1 + v3 * s1;
    float r2 = -v0 * s0 + v2 * c0;
    float r3 = -v1 * s1 + v3 * c1;

    float ss = r0 * r0 + r1 * r1 + r2 * r2 + r3 * r3;
#pragma unroll
    for (int o = 16; o; o >>= 1) ss += __shfl_xor_sync(0xffffffffu, ss, o);
    float sc = rsqrtf(ss * (1.0f / 128.0f) + 1e-6f);
    r0 *= sc; r1 *= sc; r2 *= sc; r3 *= sc;

    float* dst = (qk ? g_Kn : g_Qn) + ((size_t)h * TT + t) * DD;
    dst[lane] = r0; dst[lane + 32] = r1; dst[lane + 64] = r2; dst[lane + 96] = r3;

    int code = 0;
    float margin = 1e30f;
#pragma unroll
    for (int k = 0; k < NBITS; k++) {
        float z = r0 * Wd[k * DD + lane] + r1 * Wd[k * DD + lane + 32]
                + r2 * Wd[k * DD + lane + 64] + r3 * Wd[k * DD + lane + 96];
#pragma unroll
        for (int o = 16; o; o >>= 1) z += __shfl_xor_sync(0xffffffffu, z, o);
        float sg = 1.0f / (1.0f + expf(-z));
        float u = sg * 1.99f;
        int bit = (int)floorf(u);
        margin = fminf(margin, fabsf(u - 1.0f));
        code += bit << k;
    }
    if (lane == 0) {
        (qk ? g_kc : g_qc)[h * TT + t] = code;
        if (margin < 2e-4f) {
            int idx = atomicAdd(&g_fixcnt, 1);
            if (idx < FIXCAP) g_fixlist[idx] = (qk << 20) | (h << 16) | t;
        }
    }
}

// ---------------- exact FFMA recompute of flagged raw rows ----------------
// CRITICAL: per output element, single fp32 accumulator, fma over k ascending —
// the ordering that matched the reference's code bits (rounds 2/5/7/8). Only the
// MEMORY PATH changed: W is staged through smem in coalesced 128x64 tiles
// (stride-65 rows -> consume phase bank-conflict-free), x staged once.
__global__ __launch_bounds__(128) void k_fix_raw(const float* __restrict__ x,
                                                 const float* __restrict__ Wq,
                                                 const float* __restrict__ Wk)
{
    __shared__ float sx[CC];
    __shared__ float sW[128 * (KT + 1)];
    int b = blockIdx.x;
    int cnt = g_fixcnt;
    if (cnt > FIXCAP) cnt = FIXCAP;
    if (b >= cnt) return;
    int e = g_fixlist[b];
    int qk = (e >> 20) & 1;
    int h = (e >> 16) & 15;
    int t = e & 0xFFFF;
    const int tid = threadIdx.x;

    // stage shared x row (coalesced)
    const float4* xr4 = (const float4*)(x + (size_t)t * CC);
    float4* sx4 = (float4*)sx;
#pragma unroll
    for (int i = 0; i < 4; i++) sx4[tid + 128 * i] = xr4[tid + 128 * i];

    const float* W = qk ? Wk : Wq;
    const float4* W4 = (const float4*)(W + (size_t)h * DD * CC);  // 128 rows x CC
    float* dst = (qk ? g_Kraw : g_Qraw) + (size_t)t * CC + h * DD;

    float acc = 0.f;
    for (int k0 = 0; k0 < CC; k0 += KT) {
        __syncthreads();
        // cooperative coalesced copy of W[0:128][k0:k0+KT] into sW
#pragma unroll
        for (int i = 0; i < 16; i++) {
            int slot = tid + 128 * i;
            int row = slot >> 4, c4 = slot & 15;
            float4 v = W4[(size_t)row * (CC / 4) + (k0 >> 2) + c4];
            float* p = &sW[row * (KT + 1) + c4 * 4];
            p[0] = v.x; p[1] = v.y; p[2] = v.z; p[3] = v.w;
        }
        __syncthreads();
        const float* wrow = &sW[tid * (KT + 1)];
        const float* xk = &sx[k0];
#pragma unroll
        for (int kk = 0; kk < KT; kk++)
            acc = fmaf(xk[kk], wrow[kk], acc);
    }
    dst[tid] = acc;
}

// ---------------- rope/norm/code recompute for flagged rows only ----------------
__global__ __launch_bounds__(32) void k_rope_fix(const float* __restrict__ cosb,
                                                 const float* __restrict__ sinb,
                                                 const float* __restrict__ Wdq,
                                                 const float* __restrict__ Wdk)
{
    int b = blockIdx.x;
    int cnt = g_fixcnt;
    if (cnt > FIXCAP) cnt = FIXCAP;
    if (b >= cnt) return;
    int e = g_fixlist[b];
    int qk = (e >> 20) & 1;
    int h = (e >> 16) & 15;
    int t = e & 0xFFFF;
    int lane = threadIdx.x;

    const float* src = (qk ? g_Kraw : g_Qraw) + (size_t)t * CC + h * DD;
    const float* Wd = qk ? Wdk : Wdq;

    float v0 = src[lane], v1 = src[lane + 32], v2 = src[lane + 64], v3 = src[lane + 96];
    float c0 = cosb[t * 64 + lane],      s0 = sinb[t * 64 + lane];
    float c1 = cosb[t * 64 + lane + 32], s1 = sinb[t * 64 + lane + 32];

    float r0 =  v0 * c0 + v2 * s0;
    float r1 =  v1 * c1 + v3 * s1;
    float r2 = -v0 * s0 + v2 * c0;
    float r3 = -v1 * s1 + v3 * c1;

    float ss = r0 * r0 + r1 * r1 + r2 * r2 + r3 * r3;
#pragma unroll
    for (int o = 16; o; o >>= 1) ss += __shfl_xor_sync(0xffffffffu, ss, o);
    float sc = rsqrtf(ss * (1.0f / 128.0f) + 1e-6f);
    r0 *= sc; r1 *= sc; r2 *= sc; r3 *= sc;

    float* dst = (qk ? g_Kn : g_Qn) + ((size_t)h * TT + t) * DD;
    dst[lane] = r0; dst[lane + 32] = r1; dst[lane + 64] = r2; dst[lane + 96] = r3;

    int code = 0;
#pragma unroll
    for (int k = 0; k < NBITS; k++) {
        float z = r0 * Wd[k * DD + lane] + r1 * Wd[k * DD + lane + 32]
                + r2 * Wd[k * DD + lane + 64] + r3 * Wd[k * DD + lane + 96];
#pragma unroll
        for (int o = 16; o; o >>= 1) z += __shfl_xor_sync(0xffffffffu, z, o);
        float sg = 1.0f / (1.0f + expf(-z));
        int bit = (int)floorf(sg * 1.99f);
        code += bit << k;
    }
    if (lane == 0) (qk ? g_kc : g_qc)[h * TT + t] = code;
}

// ---------------- V transpose (2048x2048) ----------------
__global__ void k_transpose()
{
    __shared__ float tile[32][33];
    int x = blockIdx.x * 32 + threadIdx.x;
    int y = blockIdx.y * 32 + threadIdx.y;
#pragma unroll
    for (int i = 0; i < 32; i += 8)
        tile[threadIdx.y + i][threadIdx.x] = g_Vraw[(size_t)(y + i) * CC + x];
    __syncthreads();
    x = blockIdx.y * 32 + threadIdx.x;
    y = blockIdx.x * 32 + threadIdx.y;
#pragma unroll
    for (int i = 0; i < 32; i += 8)
        g_Vt[(size_t)(y + i) * TT + x] = tile[threadIdx.x][threadIdx.y + i];
}

// ---------------- row softmax (handles fully-masked rows -> zeros) ----------------
__global__ __launch_bounds__(128) void k_softmax()
{
    int row = blockIdx.x;          // h*T + q
    int h = row >> 11;
    int q = row & 2047;
    float* S = g_S + (size_t)h * TT * TT + (size_t)q * TT;
    int jmax = ((q >> 7) + 1) << 7;
    int tid = threadIdx.x;

    __shared__ float smax[4];
    __shared__ float ssum[4];

    float m = -1e30f;
    for (int j = tid; j < jmax; j += 128) m = fmaxf(m, S[j]);
#pragma unroll
    for (int o = 16; o; o >>= 1) m = fmaxf(m, __shfl_xor_sync(0xffffffffu, m, o));
    if ((tid & 31) == 0) smax[tid >> 5] = m;
    __syncthreads();
    m = fmaxf(fmaxf(smax[0], smax[1]), fmaxf(smax[2], smax[3]));

    if (m <= -1e29f) {
        for (int j = tid; j < jmax; j += 128) S[j] = 0.0f;
        return;
    }

    float e[16];
    float sum = 0.f;
    int cnt = 0;
    for (int j = tid; j < jmax; j += 128) {
        float v = expf(S[j] - m);
        e[cnt++] = v;
        sum += v;
    }
#pragma unroll
    for (int o = 16; o; o >>= 1) sum += __shfl_xor_sync(0xffffffffu, sum, o);
    if ((tid & 31) == 0) ssum[tid >> 5] = sum;
    __syncthreads();
    sum = ssum[0] + ssum[1] + ssum[2] + ssum[3];

    float inv = 1.0f / sum;
    cnt = 0;
    for (int j = tid; j < jmax; j += 128) S[j] = e[cnt++] * inv;
}

// ---------------- launch ----------------
extern "C" void kernel_launch(void* const* d_in, const int* in_sizes, int n_in,
                              void* d_out, int out_size)
{
    const float* x     = (const float*)d_in[0];
    const float* cosb  = (const float*)d_in[1];
    const float* sinb  = (const float*)d_in[2];
    const float* Wq    = (const float*)d_in[3];
    const float* Wk    = (const float*)d_in[4];
    const float* Wv    = (const float*)d_in[5];
    const float* Wproj = (const float*)d_in[6];
    const float* Wdq   = (const float*)d_in[7];
    const float* Wdk   = (const float*)d_in[8];
    float* out = (float*)d_out;

    k_zero_cnt<<<1, 1>>>();
    k_qkv_tc<<<dim3(16, 16, 3), 256>>>(x, Wq, Wk, Wv);

    // codes + margin flagging (all rows)
    k_ropenorm<<<(2 * TT * HH) / 8, 256>>>(cosb, sinb, Wdq, Wdk);
    // reference-ordering fp32 recompute of flagged raw rows, then their rope/codes
    k_fix_raw<<<FIXCAP, 128>>>(x, Wq, Wk);
    k_rope_fix<<<FIXCAP, 32>>>(cosb, sinb, Wdq, Wdk);

    k_transpose<<<dim3(64, 64), dim3(32, 8)>>>();

    k_scores_tc<<<dim3(16, 16, HH), 256>>>();
    k_softmax<<<HH * TT, 128>>>();
    k_pv_tc<<<dim3(1, 16, HH), 256>>>();

    k_proj_tc<<<dim3(16, 16, 1), 256>>>(Wproj, out);
}